// round 15
// baseline (speedup 1.0000x reference)
#include <cuda_runtime.h>
#include <cuda_fp16.h>
#include <cstdint>

#define DI __device__ __forceinline__

// Problem dims (fixed): B=8, H=8, T=4096, D=128.
// y[b,i,t,e] = beta[e] * sum_j sign[i,j] * sum_d x[b,j,t,d] * W[i^j][d,e]
// (WEIGHT_IDX[i][j] == i ^ j)
//
// Harness targets plain sm_103 (no tcgen05). cp.async + ldmatrix + mma.sync.
// R12: 247.9us (occ1). R13: 209.4us (occ2). Model: HMMA-issue floor ~119us +
// ldsm-chain bubbles. R14: N=256/CTA (warp tile 64x64, 32-long mma runs),
// A+B fragment double-buffering, merged prep kernel.

// ---------------- scratch (device globals; no cudaMalloc anywhere) ----------
__device__ __align__(1024) __half g_xh[(size_t)8 * 8 * 4096 * 128]; // x fp16, 64 MB
__device__ __align__(1024) __half g_Bh[64 * 128 * 128];             // [i][j][e][d], 2 MB

__constant__ float c_sign[64] = {
    +1, -1, -1, -1, -1, -1, -1, -1,
    +1, +1, +1, -1, +1, -1, -1, +1,
    +1, -1, +1, +1, +1, +1, -1, -1,
    +1, +1, -1, +1, +1, -1, +1, -1,
    +1, -1, -1, -1, +1, +1, +1, +1,
    +1, +1, -1, +1, -1, +1, -1, +1,
    +1, +1, +1, -1, -1, +1, +1, -1,
    +1, -1, +1, +1, -1, -1, +1, +1};

// ---------------- helpers ----------------------------------------------------
DI uint32_t smem_u32(const void* p) {
    uint32_t a;
    asm("{ .reg .u64 t; cvta.to.shared.u64 t, %1; cvt.u32.u64 %0, t; }"
        : "=r"(a) : "l"(p));
    return a;
}
DI uint32_t sw128(uint32_t o) { return o ^ ((o >> 3) & 0x70); }

DI void cpasync16(uint32_t s, const void* g) {
    asm volatile("cp.async.cg.shared.global [%0], [%1], 16;"
                 :: "r"(s), "l"(g) : "memory");
}
DI void cp_commit() { asm volatile("cp.async.commit_group;" ::: "memory"); }

DI void ldsm4(uint32_t& r0, uint32_t& r1, uint32_t& r2, uint32_t& r3,
              uint32_t addr) {
    asm volatile("ldmatrix.sync.aligned.m8n8.x4.shared.b16 {%0,%1,%2,%3}, [%4];"
                 : "=r"(r0), "=r"(r1), "=r"(r2), "=r"(r3) : "r"(addr));
}

DI void mma16816(float* d, const uint32_t* a, uint32_t b0, uint32_t b1) {
    asm volatile(
        "mma.sync.aligned.m16n8k16.row.col.f32.f16.f16.f32 "
        "{%0,%1,%2,%3}, {%4,%5,%6,%7}, {%8,%9}, {%0,%1,%2,%3};"
        : "+f"(d[0]), "+f"(d[1]), "+f"(d[2]), "+f"(d[3])
        : "r"(a[0]), "r"(a[1]), "r"(a[2]), "r"(a[3]), "r"(b0), "r"(b1));
}

// ---------------- merged prep kernel -----------------------------------------
// 1) x fp32 -> fp16 (g_xh), 2) Bh[i][j][e][d] = sign[i,j]*W[i^j][d][e] fp16.
__global__ void k_prep(const float* __restrict__ W, const float4* __restrict__ x4) {
    const int stride = gridDim.x * blockDim.x;
    const int t = blockIdx.x * blockDim.x + threadIdx.x;

    uint2* o = reinterpret_cast<uint2*>(g_xh);
    const int n4 = 8 * 8 * 4096 * 128 / 4;
    for (int i = t; i < n4; i += stride) {
        float4 v = x4[i];
        __half2 a = __floats2half2_rn(v.x, v.y);
        __half2 b = __floats2half2_rn(v.z, v.w);
        uint2 u;
        u.x = *reinterpret_cast<const unsigned*>(&a);
        u.y = *reinterpret_cast<const unsigned*>(&b);
        o[i] = u;
    }

    for (int idx = t; idx < 64 * 128 * 128; idx += stride) {
        int d  = idx & 127;
        int e  = (idx >> 7) & 127;
        int ij = idx >> 14;
        int i = ij >> 3, j = ij & 7;
        float w = W[(size_t)((i ^ j) * 128 + d) * 128 + e] * c_sign[ij];
        g_Bh[idx] = __float2half_rn(w);
    }
}

// ---------------- GEMM kernel ------------------------------------------------
// CTA: b=blockIdx.z, head-pair i0=2*blockIdx.y, t-tile t0=blockIdx.x*128.
// Tile M=128 x N=256 x K=1024 (16 k-chunks of 64 halves).
// 8 warps as 2(M) x 4(N); warp tile 64x64 via mma.m16n8k16 (4x8 frags).
// 3-stage cp.async pipeline; stage = A[128x64] 16KB + B[256x64] 32KB = 48KB.
// Fragments double-buffered across kk (prefetch kk+1 before mma of kk).
static constexpr uint32_t STG = 49152;             // 48 KB
static constexpr uint32_t SMEM_TOTAL = 3 * STG;    // 144 KB

__global__ void __launch_bounds__(256, 1)
k_gemm(const float* __restrict__ beta, float* __restrict__ out) {
    extern __shared__ char smem[];
    const uint32_t sb = smem_u32(smem);
    const int tid = threadIdx.x, wid = tid >> 5, lane = tid & 31;
    const int t0 = blockIdx.x * 128;
    const int i0 = blockIdx.y * 2;
    const int b  = blockIdx.z;
    const int wm = wid >> 2, wn = wid & 3;

    const __half* xb = g_xh + ((size_t)b * 8 * 4096 + t0) * 128;

    auto load_stage = [&](int s) {
        const int j = s >> 1, dh = s & 1;
        const uint32_t base = sb + (uint32_t)(s % 3) * STG;
        const __half* aS = xb + (size_t)j * 4096 * 128 + dh * 64;   // +t*128
#pragma unroll
        for (int k = 0; k < 12; k++) {
            int c  = tid + k * 256;            // 0..3071
            int cc = c & 7;                    // 16B chunk in 128B row
            if (c < 1024) {                    // A: rows 0..127
                int r = c >> 3;
                cpasync16(base + sw128((uint32_t)r * 128 + cc * 16),
                          aS + (size_t)r * 128 + cc * 8);
            } else {                           // B: n 0..255 over 2 heads
                int n = (c - 1024) >> 3;
                int h = n >> 7, e = n & 127;
                const __half* src = g_Bh +
                    (((size_t)(i0 + h) * 8 + j) * 128 + e) * 128 + dh * 64 + cc * 8;
                cpasync16(base + 16384u + sw128((uint32_t)n * 128 + cc * 16), src);
            }
        }
        cp_commit();
    };

    float d[4][8][4] = {};
    uint32_t af[2][4][4], bfr[2][4][4];

    // ldmatrix lane->address maps (match PTX mma fragment layouts)
    const uint32_t a_row = (uint32_t)(wm * 64 + (lane & 15));
    const uint32_t a_k   = (uint32_t)((lane >> 4) * 16);
    const uint32_t b_row = (uint32_t)(wn * 64 + ((lane >> 4) << 3) + (lane & 7));
    const uint32_t b_k   = (uint32_t)(((lane >> 3) & 1) * 16);

    load_stage(0);
    load_stage(1);

#pragma unroll 1
    for (int s = 0; s < 16; s++) {
        if (s < 15) asm volatile("cp.async.wait_group 1;" ::: "memory");
        else        asm volatile("cp.async.wait_group 0;" ::: "memory");
        __syncthreads();

        if (s + 2 <= 15) load_stage(s + 2);   // buffer (s+2)%3 == (s-1)%3, free

        const uint32_t Ab  = sb + (uint32_t)(s % 3) * STG;
        const uint32_t Bbs = Ab + 16384u;

        auto load_frags = [&](int buf, int kk) {
#pragma unroll
            for (int mf = 0; mf < 4; mf++) {
                uint32_t byte = (a_row + mf * 16u) * 128u + kk * 32u + a_k;
                ldsm4(af[buf][mf][0], af[buf][mf][1], af[buf][mf][2],
                      af[buf][mf][3], Ab + sw128(byte));
            }
#pragma unroll
            for (int bb = 0; bb < 4; bb++) {
                uint32_t byte = (b_row + bb * 16u) * 128u + kk * 32u + b_k;
                ldsm4(bfr[buf][bb][0], bfr[buf][bb][1], bfr[buf][bb][2],
                      bfr[buf][bb][3], Bbs + sw128(byte));
            }
        };

        load_frags(0, 0);
#pragma unroll
        for (int kk = 0; kk < 4; kk++) {
            const int cur = kk & 1;
            if (kk < 3) load_frags(cur ^ 1, kk + 1);   // prefetch next kk
#pragma unroll
            for (int mf = 0; mf < 4; mf++)
#pragma unroll
                for (int nf = 0; nf < 8; nf++)
                    mma16816(d[mf][nf], af[cur][mf],
                             bfr[cur][nf >> 1][(nf & 1) * 2],
                             bfr[cur][nf >> 1][(nf & 1) * 2 + 1]);
        }
    }

    // ---------------- epilogue: direct float2 stores with beta --------------
    const float2* be2 = reinterpret_cast<const float2*>(beta);
    const int g = lane >> 2, tig = lane & 3;
#pragma unroll
    for (int nf = 0; nf < 8; nf++) {
        const int n = wn * 64 + nf * 8 + tig * 2;   // 0..255
        const int head = n >> 7, e0 = n & 127;
        const float2 bt = be2[e0 >> 1];
        float* ob = out + ((size_t)b * 8 + i0 + head) * 4096 * 128;
#pragma unroll
        for (int mf = 0; mf < 4; mf++) {
            const int r0 = t0 + wm * 64 + mf * 16 + g;
            float2 v0 = make_float2(d[mf][nf][0] * bt.x, d[mf][nf][1] * bt.y);
            float2 v1 = make_float2(d[mf][nf][2] * bt.x, d[mf][nf][3] * bt.y);
            *reinterpret_cast<float2*>(ob + (size_t)r0 * 128 + e0) = v0;
            *reinterpret_cast<float2*>(ob + (size_t)(r0 + 8) * 128 + e0) = v1;
        }
    }
}

// ---------------- launch -----------------------------------------------------
extern "C" void kernel_launch(void* const* d_in, const int* in_sizes, int n_in,
                              void* d_out, int out_size) {
    const float* x    = (const float*)d_in[0];
    const float* W    = (const float*)d_in[1];
    const float* beta = (const float*)d_in[2];
    float* out = (float*)d_out;

    cudaFuncSetAttribute(k_gemm, cudaFuncAttributeMaxDynamicSharedMemorySize,
                         (int)SMEM_TOTAL);

    k_prep<<<2048, 256>>>(W, (const float4*)x);
    k_gemm<<<dim3(32, 4, 8), 256, SMEM_TOTAL>>>(beta, out);
}

// round 16
// speedup vs baseline: 1.0573x; 1.0573x over previous
#include <cuda_runtime.h>
#include <cuda_fp16.h>
#include <cstdint>

#define DI __device__ __forceinline__

// Problem dims (fixed): B=8, H=8, T=4096, D=128.
// y[b,i,t,e] = beta[e] * sum_j sign[i,j] * sum_d x[b,j,t,d] * W[i^j][d,e]
// (WEIGHT_IDX[i][j] == i ^ j)
//
// Harness targets plain sm_103 (no tcgen05). cp.async + ldmatrix + mma.sync.
// R12: 247.9us (occ1). R13: 209.4us (occ2, tensor~66%). R15: N=256+dblbuf
// regressed (242 regs -> occ1, tensor 61%; HMMA floor ~113us measured).
// R16: back to occ2/N=128 + A-frag double-buffer (+16 regs, fits 128) +
// stage-head reorder + beta folded into weights.

// ---------------- scratch (device globals; no cudaMalloc anywhere) ----------
__device__ __align__(1024) __half g_xh[(size_t)8 * 8 * 4096 * 128]; // x fp16, 64 MB
__device__ __align__(1024) __half g_Bh[64 * 128 * 128];             // [i][j][e][d], 2 MB

__constant__ float c_sign[64] = {
    +1, -1, -1, -1, -1, -1, -1, -1,
    +1, +1, +1, -1, +1, -1, -1, +1,
    +1, -1, +1, +1, +1, +1, -1, -1,
    +1, +1, -1, +1, +1, -1, +1, -1,
    +1, -1, -1, -1, +1, +1, +1, +1,
    +1, +1, -1, +1, -1, +1, -1, +1,
    +1, +1, +1, -1, -1, +1, +1, -1,
    +1, -1, +1, +1, -1, -1, +1, +1};

// ---------------- helpers ----------------------------------------------------
DI uint32_t smem_u32(const void* p) {
    uint32_t a;
    asm("{ .reg .u64 t; cvta.to.shared.u64 t, %1; cvt.u32.u64 %0, t; }"
        : "=r"(a) : "l"(p));
    return a;
}
DI uint32_t sw128(uint32_t o) { return o ^ ((o >> 3) & 0x70); }

DI void cpasync16(uint32_t s, const void* g) {
    asm volatile("cp.async.cg.shared.global [%0], [%1], 16;"
                 :: "r"(s), "l"(g) : "memory");
}
DI void cp_commit() { asm volatile("cp.async.commit_group;" ::: "memory"); }

DI void ldsm4(uint32_t& r0, uint32_t& r1, uint32_t& r2, uint32_t& r3,
              uint32_t addr) {
    asm volatile("ldmatrix.sync.aligned.m8n8.x4.shared.b16 {%0,%1,%2,%3}, [%4];"
                 : "=r"(r0), "=r"(r1), "=r"(r2), "=r"(r3) : "r"(addr));
}

DI void mma16816(float* d, const uint32_t* a, uint32_t b0, uint32_t b1) {
    asm volatile(
        "mma.sync.aligned.m16n8k16.row.col.f32.f16.f16.f32 "
        "{%0,%1,%2,%3}, {%4,%5,%6,%7}, {%8,%9}, {%0,%1,%2,%3};"
        : "+f"(d[0]), "+f"(d[1]), "+f"(d[2]), "+f"(d[3])
        : "r"(a[0]), "r"(a[1]), "r"(a[2]), "r"(a[3]), "r"(b0), "r"(b1));
}

// ---------------- merged prep kernel -----------------------------------------
// 1) x fp32 -> fp16 (g_xh)
// 2) Bh[i][j][e][d] = sign[i,j] * W[i^j][d][e] * beta[e]  (beta folded in)
__global__ void k_prep(const float* __restrict__ W, const float4* __restrict__ x4,
                       const float* __restrict__ beta) {
    const int stride = gridDim.x * blockDim.x;
    const int t = blockIdx.x * blockDim.x + threadIdx.x;

    uint2* o = reinterpret_cast<uint2*>(g_xh);
    const int n4 = 8 * 8 * 4096 * 128 / 4;
    for (int i = t; i < n4; i += stride) {
        float4 v = x4[i];
        __half2 a = __floats2half2_rn(v.x, v.y);
        __half2 b = __floats2half2_rn(v.z, v.w);
        uint2 u;
        u.x = *reinterpret_cast<const unsigned*>(&a);
        u.y = *reinterpret_cast<const unsigned*>(&b);
        o[i] = u;
    }

    for (int idx = t; idx < 64 * 128 * 128; idx += stride) {
        int d  = idx & 127;
        int e  = (idx >> 7) & 127;
        int ij = idx >> 14;
        int i = ij >> 3, j = ij & 7;
        float w = W[(size_t)((i ^ j) * 128 + d) * 128 + e] * c_sign[ij] * beta[e];
        g_Bh[idx] = __float2half_rn(w);
    }
}

// ---------------- GEMM kernel ------------------------------------------------
// CTA: b=blockIdx.z, head i=blockIdx.y, t-tile t0=blockIdx.x*128.
// Tile M=128 x N=128 x K=1024 (16 k-chunks of 64 halves).
// 8 warps as 2(M) x 4(N); warp tile 64x32 via mma.m16n8k16.
// 3-stage cp.async pipeline (32KB/stage, 96KB total) -> 2 CTAs/SM.
// A fragments double-buffered across kk; B reloaded per kk after WAR clears.
static constexpr uint32_t SMEM_TOTAL = 3 * 32768;  // 96 KB

__global__ void __launch_bounds__(256, 2)
k_gemm(float* __restrict__ out) {
    extern __shared__ char smem[];
    const uint32_t sb = smem_u32(smem);
    const int tid = threadIdx.x, wid = tid >> 5, lane = tid & 31;
    const int t0 = blockIdx.x * 128;
    const int ih = blockIdx.y;
    const int b  = blockIdx.z;
    const int wm = wid >> 2, wn = wid & 3;

    const __half* xb  = g_xh + ((size_t)b * 8 * 4096 + t0) * 128;
    const __half* Bhp = g_Bh + (size_t)ih * 8 * 16384;

    auto load_stage = [&](int s) {
        const int j = s >> 1, dh = s & 1;
        const uint32_t base = sb + (uint32_t)(s % 3) * 32768u;
        const __half* aS = xb  + (size_t)j * 4096 * 128 + dh * 64;  // +r*128
        const __half* bS = Bhp + (size_t)j * 16384      + dh * 64;  // +n*128
#pragma unroll
        for (int k = 0; k < 8; k++) {
            int c  = tid + k * 256;            // 0..2047
            int cc = c & 7;                    // 16B chunk in 128B row
            int r  = (c >> 3) & 127;           // row (A) or n (B)
            if (c < 1024)
                cpasync16(base + sw128((uint32_t)r * 128 + cc * 16),
                          aS + (size_t)r * 128 + cc * 8);
            else
                cpasync16(base + 16384u + sw128((uint32_t)r * 128 + cc * 16),
                          bS + (size_t)r * 128 + cc * 8);
        }
        cp_commit();
    };

    float d[4][4][4] = {};
    uint32_t af[2][4][4];   // double-buffered A fragments
    uint32_t bf[2][4];      // single-buffered B fragments (per kk)

    // ldmatrix lane->address maps (match PTX mma fragment layouts; R13-proven)
    const uint32_t a_row = (uint32_t)(wm * 64 + (lane & 15));
    const uint32_t a_k   = (uint32_t)((lane >> 4) * 16);
    const uint32_t b_row = (uint32_t)(wn * 32 + ((lane >> 4) << 3) + (lane & 7));
    const uint32_t b_k   = (uint32_t)(((lane >> 3) & 1) * 16);

    load_stage(0);
    load_stage(1);

#pragma unroll 1
    for (int s = 0; s < 16; s++) {
        if (s < 15) asm volatile("cp.async.wait_group 1;" ::: "memory");
        else        asm volatile("cp.async.wait_group 0;" ::: "memory");
        __syncthreads();

        const uint32_t Ab  = sb + (uint32_t)(s % 3) * 32768u;
        const uint32_t Bbs = Ab + 16384u;

        auto ldA = [&](int buf, int kk) {
#pragma unroll
            for (int mf = 0; mf < 4; mf++) {
                uint32_t byte = (a_row + mf * 16u) * 128u + kk * 32u + a_k;
                ldsm4(af[buf][mf][0], af[buf][mf][1], af[buf][mf][2],
                      af[buf][mf][3], Ab + sw128(byte));
            }
        };
        auto ldB = [&](int kk) {
#pragma unroll
            for (int bb = 0; bb < 2; bb++) {
                uint32_t byte = (b_row + bb * 16u) * 128u + kk * 32u + b_k;
                ldsm4(bf[bb][0], bf[bb][1], bf[bb][2], bf[bb][3],
                      Bbs + sw128(byte));
            }
        };

        // kk0 fragments first, then cp.asyncs (LDGSTS issue covers ldsm lat)
        ldA(0, 0);
        ldB(0);
        if (s + 2 <= 15) load_stage(s + 2);   // buffer (s+2)%3 == (s-1)%3, free

#pragma unroll
        for (int kk = 0; kk < 4; kk++) {
            const int cur = kk & 1;
            if (kk < 3) ldA(cur ^ 1, kk + 1);  // prefetch next A
#pragma unroll
            for (int mf = 0; mf < 4; mf++)
#pragma unroll
                for (int nf = 0; nf < 4; nf++)
                    mma16816(d[mf][nf], af[cur][mf],
                             bf[nf >> 1][(nf & 1) * 2],
                             bf[nf >> 1][(nf & 1) * 2 + 1]);
            if (kk < 3) ldB(kk + 1);           // WAR on bf cleared by mma issue
        }
    }

    // ---------------- epilogue: direct float2 stores (beta pre-folded) -----
    const int g = lane >> 2, tig = lane & 3;
    float* ob = out + ((size_t)b * 8 + ih) * 4096 * 128;
#pragma unroll
    for (int nf = 0; nf < 4; nf++) {
        const int e0 = wn * 32 + nf * 8 + tig * 2;
#pragma unroll
        for (int mf = 0; mf < 4; mf++) {
            const int r0 = t0 + wm * 64 + mf * 16 + g;
            float2 v0 = make_float2(d[mf][nf][0], d[mf][nf][1]);
            float2 v1 = make_float2(d[mf][nf][2], d[mf][nf][3]);
            *reinterpret_cast<float2*>(ob + (size_t)r0 * 128 + e0) = v0;
            *reinterpret_cast<float2*>(ob + (size_t)(r0 + 8) * 128 + e0) = v1;
        }
    }
}

// ---------------- launch -----------------------------------------------------
extern "C" void kernel_launch(void* const* d_in, const int* in_sizes, int n_in,
                              void* d_out, int out_size) {
    const float* x    = (const float*)d_in[0];
    const float* W    = (const float*)d_in[1];
    const float* beta = (const float*)d_in[2];
    float* out = (float*)d_out;

    cudaFuncSetAttribute(k_gemm, cudaFuncAttributeMaxDynamicSharedMemorySize,
                         (int)SMEM_TOTAL);

    k_prep<<<2048, 256>>>(W, (const float4*)x, beta);
    k_gemm<<<dim3(32, 8, 8), 256, SMEM_TOTAL>>>(out);
}